// round 16
// baseline (speedup 1.0000x reference)
#include <cuda_runtime.h>
#include <cuda_bf16.h>
#include <math.h>

// Problem dims
#define TT 512
#define BB 64
#define II 512
#define HH 512

// ---------------- device scratch ----------------
__device__ float g_xz[TT * BB];   // [t][b] includes zt_w_b
__device__ float g_xr[TT * BB];   // [t][b] includes rt_w_b

// ---------------- helpers ----------------
typedef unsigned long long ull;
union U64F2 { ull u; float2 f; };
union QU    { uint4 q; ull u[2]; };

__device__ __forceinline__ void fma2(ull& d, ull a, ull b) {
    asm("fma.rn.f32x2 %0, %1, %2, %0;" : "+l"(d) : "l"(a), "l"(b));
}
__device__ __forceinline__ ull pack2(float lo, float hi) {
    ull r; asm("mov.b64 %0, {%1, %2};" : "=l"(r) : "f"(lo), "f"(hi)); return r;
}
__device__ __forceinline__ float sigmoid_fast(float x) {
    float e, r;
    asm("ex2.approx.f32 %0, %1;" : "=f"(e) : "f"(-1.4426950408889634f * x));
    asm("rcp.approx.f32 %0, %1;" : "=f"(r) : "f"(1.0f + e));
    return r;
}
__device__ __forceinline__ float tanh_fast(float x) {
    float e, r;
    asm("ex2.approx.f32 %0, %1;" : "=f"(e) : "f"(-2.8853900817779268f * x));
    asm("rcp.approx.f32 %0, %1;" : "=f"(r) : "f"(1.0f + e));
    return fmaf(2.0f, r, -1.0f);
}
__device__ __forceinline__ unsigned smem_u32(const void* p) {
    return (unsigned)__cvta_generic_to_shared(p);
}
__device__ __forceinline__ void bar_sync(int id, int cnt) {
    asm volatile("bar.sync %0, %1;" :: "r"(id), "r"(cnt) : "memory");
}
__device__ __forceinline__ void bar_arrive(int id, int cnt) {
    asm volatile("bar.arrive %0, %1;" :: "r"(id), "r"(cnt) : "memory");
}
__device__ __forceinline__ unsigned pack_bf16x2(float v_lo, float v_hi) {
    unsigned r;
    asm("cvt.rn.bf16x2.f32 %0, %1, %2;" : "=r"(r) : "f"(v_hi), "f"(v_lo));
    return r;
}

// ---------------- kernel 1: gate input projections xz, xr ----------------
__global__ void gate_pre_kernel(const float* __restrict__ in,
                                const float* __restrict__ zw, const float* __restrict__ zb,
                                const float* __restrict__ rw, const float* __restrict__ rb) {
    int row  = blockIdx.x * 8 + (threadIdx.x >> 5);
    int lane = threadIdx.x & 31;
    const float4* a4 = (const float4*)(in + (size_t)row * II);
    const float4* z4 = (const float4*)zw;
    const float4* r4 = (const float4*)rw;
    float az = 0.f, ar = 0.f;
#pragma unroll 4
    for (int i = lane; i < II / 4; i += 32) {
        float4 v = a4[i];
        float4 z = z4[i];
        float4 r = r4[i];
        az += v.x * z.x + v.y * z.y + v.z * z.z + v.w * z.w;
        ar += v.x * r.x + v.y * r.y + v.z * r.z + v.w * r.w;
    }
#pragma unroll
    for (int off = 16; off >= 1; off >>= 1) {
        az += __shfl_xor_sync(0xffffffffu, az, off);
        ar += __shfl_xor_sync(0xffffffffu, ar, off);
    }
    if (lane == 0) {
        g_xz[row] = az + zb[0];
        g_xr[row] = ar + rb[0];
    }
}

// ---------------- kernel 2: xn GEMM via mma.sync bf16, split-bf16 --------
#define MMA_OP(c, a, b)                                                       \
    asm volatile("mma.sync.aligned.m16n8k16.row.col.f32.bf16.bf16.f32 "       \
                 "{%0,%1,%2,%3},{%4,%5,%6,%7},{%8,%9},{%0,%1,%2,%3};"         \
                 : "+f"(c[0]), "+f"(c[1]), "+f"(c[2]), "+f"(c[3])             \
                 : "r"(a[0]), "r"(a[1]), "r"(a[2]), "r"(a[3]),                \
                   "r"(b[0]), "r"(b[1]))

__global__ __launch_bounds__(256) void xn_gemm_mma(const float* __restrict__ A,
                                                   const float* __restrict__ W,
                                                   const float* __restrict__ bias,
                                                   float* __restrict__ C) {
    __shared__ __align__(16) unsigned short sAh[128 * 40];
    __shared__ __align__(16) unsigned short sAl[128 * 40];
    __shared__ __align__(16) unsigned short sWh[64 * 40];
    __shared__ __align__(16) unsigned short sWl[64 * 40];
    __shared__ __align__(16) float sBias[64];

    int tid  = threadIdx.x;
    int lane = tid & 31;
    int warp = tid >> 5;
    int wm   = warp >> 1;
    int wn   = warp & 1;
    int bm   = blockIdx.x * 128;
    int bn   = blockIdx.y * 64;

    if (tid < 64) sBias[tid] = bias[bn + tid];

    float acc[2][4][4];
#pragma unroll
    for (int i = 0; i < 2; i++)
#pragma unroll
        for (int j = 0; j < 4; j++)
#pragma unroll
            for (int q = 0; q < 4; q++) acc[i][j][q] = 0.f;

    int r  = lane >> 2;
    int g2 = (lane & 3) * 2;

    for (int kc = 0; kc < 16; kc++) {
        __syncthreads();
#pragma unroll
        for (int i = 0; i < 4; i++) {
            int slot = tid + i * 256;
            int row  = slot >> 3;
            int f4   = slot & 7;
            float4 v = *(const float4*)(A + (size_t)(bm + row) * 512 + kc * 32 + f4 * 4);
            float hx = __bfloat162float(__float2bfloat16(v.x));
            float hy = __bfloat162float(__float2bfloat16(v.y));
            float hz = __bfloat162float(__float2bfloat16(v.z));
            float hw = __bfloat162float(__float2bfloat16(v.w));
            *(unsigned*)(sAh + row * 40 + f4 * 4)     = pack_bf16x2(v.x, v.y);
            *(unsigned*)(sAh + row * 40 + f4 * 4 + 2) = pack_bf16x2(v.z, v.w);
            *(unsigned*)(sAl + row * 40 + f4 * 4)     = pack_bf16x2(v.x - hx, v.y - hy);
            *(unsigned*)(sAl + row * 40 + f4 * 4 + 2) = pack_bf16x2(v.z - hz, v.w - hw);
        }
#pragma unroll
        for (int i = 0; i < 2; i++) {
            int slot = tid + i * 256;
            int row  = slot >> 3;
            int f4   = slot & 7;
            float4 v = *(const float4*)(W + (size_t)(bn + row) * 512 + kc * 32 + f4 * 4);
            float hx = __bfloat162float(__float2bfloat16(v.x));
            float hy = __bfloat162float(__float2bfloat16(v.y));
            float hz = __bfloat162float(__float2bfloat16(v.z));
            float hw = __bfloat162float(__float2bfloat16(v.w));
            *(unsigned*)(sWh + row * 40 + f4 * 4)     = pack_bf16x2(v.x, v.y);
            *(unsigned*)(sWh + row * 40 + f4 * 4 + 2) = pack_bf16x2(v.z, v.w);
            *(unsigned*)(sWl + row * 40 + f4 * 4)     = pack_bf16x2(v.x - hx, v.y - hy);
            *(unsigned*)(sWl + row * 40 + f4 * 4 + 2) = pack_bf16x2(v.z - hz, v.w - hw);
        }
        __syncthreads();

#pragma unroll
        for (int ks = 0; ks < 2; ks++) {
            int k0 = ks * 16;
            unsigned Ah[2][4], Al[2][4], Bh[4][2], Bl[4][2];
#pragma unroll
            for (int mi = 0; mi < 2; mi++) {
                int rb = wm * 32 + mi * 16;
                Ah[mi][0] = *(const unsigned*)(sAh + (rb + r) * 40 + k0 + g2);
                Ah[mi][1] = *(const unsigned*)(sAh + (rb + r + 8) * 40 + k0 + g2);
                Ah[mi][2] = *(const unsigned*)(sAh + (rb + r) * 40 + k0 + g2 + 8);
                Ah[mi][3] = *(const unsigned*)(sAh + (rb + r + 8) * 40 + k0 + g2 + 8);
                Al[mi][0] = *(const unsigned*)(sAl + (rb + r) * 40 + k0 + g2);
                Al[mi][1] = *(const unsigned*)(sAl + (rb + r + 8) * 40 + k0 + g2);
                Al[mi][2] = *(const unsigned*)(sAl + (rb + r) * 40 + k0 + g2 + 8);
                Al[mi][3] = *(const unsigned*)(sAl + (rb + r + 8) * 40 + k0 + g2 + 8);
            }
#pragma unroll
            for (int ni = 0; ni < 4; ni++) {
                int cb = wn * 32 + ni * 8 + r;
                Bh[ni][0] = *(const unsigned*)(sWh + cb * 40 + k0 + g2);
                Bh[ni][1] = *(const unsigned*)(sWh + cb * 40 + k0 + g2 + 8);
                Bl[ni][0] = *(const unsigned*)(sWl + cb * 40 + k0 + g2);
                Bl[ni][1] = *(const unsigned*)(sWl + cb * 40 + k0 + g2 + 8);
            }
#pragma unroll
            for (int mi = 0; mi < 2; mi++)
#pragma unroll
                for (int ni = 0; ni < 4; ni++) {
                    MMA_OP(acc[mi][ni], Ah[mi], Bh[ni]);
                    MMA_OP(acc[mi][ni], Ah[mi], Bl[ni]);
                    MMA_OP(acc[mi][ni], Al[mi], Bh[ni]);
                }
        }
    }

#pragma unroll
    for (int mi = 0; mi < 2; mi++)
#pragma unroll
        for (int ni = 0; ni < 4; ni++) {
            int row = bm + wm * 32 + mi * 16 + r;
            int cl  = wn * 32 + ni * 8 + g2;
            int col = bn + cl;
            float2 o0, o1;
            o0.x = acc[mi][ni][0] + sBias[cl];
            o0.y = acc[mi][ni][1] + sBias[cl + 1];
            o1.x = acc[mi][ni][2] + sBias[cl];
            o1.y = acc[mi][ni][3] + sBias[cl + 1];
            *(float2*)(C + (size_t)row * 512 + col)       = o0;
            *(float2*)(C + (size_t)(row + 8) * 512 + col) = o1;
        }
}

// ---------------- kernel 3: recurrent scan, batch-group pipelined --------
// Two independent 2-batch recurrences (groups) alternate substeps so that
// each group's DSMEM exchange flight hides under the other group's compute.
// Per-group clone of the proven per-chunk mbarrier protocol (512B msgs).
#define WS_OFF   0                        // float[128 kpc][128] = 64KB
#define HP_OFF   65536                    // ull[2g][2s][512] = 16KB
#define PART_OFF 81920                    // float[4][2048] = 32KB
#define ZRP_OFF  114688                   // float[4][32] = 512B
#define ZUP_OFF  (ZRP_OFF + 512)          // ull[256]
#define RUP_OFF  (ZUP_OFF + 2048)         // ull[256]
#define HUB_OFF  (RUP_OFF + 2048)         // float[64]
#define MBAR_OFF (HUB_OFF + 256)          // 32 x b64 = [g][chunk][s]
#define SC_SMEM  (MBAR_OFF + 256)

extern __shared__ char sc_smem[];

__global__ void __cluster_dims__(8, 1, 1) __launch_bounds__(512, 1)
scan_kernel(const float* __restrict__ hidden,
            const float* __restrict__ ztu_g, const float* __restrict__ ztub,
            const float* __restrict__ rtu_g, const float* __restrict__ rtub,
            const float* __restrict__ huw, const float* __restrict__ hub_g,
            float* __restrict__ out, int tail) {
    ull*   wS   = (ull*)(sc_smem + WS_OFF);
    ull*   hpb  = (ull*)(sc_smem + HP_OFF);
    float* part = (float*)(sc_smem + PART_OFF);
    float* zrpf = (float*)(sc_smem + ZRP_OFF);
    ull*   zup  = (ull*)(sc_smem + ZUP_OFF);
    ull*   rup  = (ull*)(sc_smem + RUP_OFF);
    float* hub  = (float*)(sc_smem + HUB_OFF);

    int tid    = threadIdx.x;
    int rank   = blockIdx.x & 7;
    int grp    = blockIdx.x >> 3;
    int jjbase = rank * 64;
    unsigned mbase = smem_u32(sc_smem + MBAR_OFF);
    unsigned hpb_a = smem_u32(hpb);

    int lane = tid & 31;
    int warp = tid >> 5;
    int jjp  = lane;
    int ks   = warp;
    int gate = warp & 1;
    int ks8  = warp >> 1;
    int chnk = warp >> 1;
    int own  = (chnk == rank);
    int b1cnt = 128 + ((rank >= 2) ? 64 : 0);   // warps 0-3 + own warps if >=4

    // -------- prologue: W (half smem, half regs), gate weights, h(0) ------
    for (int i = tid; i < 64 * 512; i += 512) {
        int jj = i >> 9, k = i & 511;
        int kp = k >> 1, kpl = kp & 15;
        if (kpl >= 8) {
            int kpc = (kp >> 4) * 8 + (kpl - 8);
            ((float*)wS)[kpc * 128 + jj * 2 + (k & 1)] = huw[(size_t)(jjbase + jj) * HH + k];
        }
    }
    ull wreg[16];
    {
        const float* wr0 = huw + (size_t)(jjbase + 2 * jjp) * HH + ks * 32;
        const float* wr1 = wr0 + HH;
#pragma unroll
        for (int i = 0; i < 8; i++) {
            wreg[2 * i]     = *(const ull*)(wr0 + 2 * i);
            wreg[2 * i + 1] = *(const ull*)(wr1 + 2 * i);
        }
    }
    if (tid < 256) zup[tid] = ((const ull*)ztu_g)[tid];
    else           rup[tid - 256] = ((const ull*)rtu_g)[tid - 256];
    // h(0): hpb[g][0][kp*2+b] for group batches grp*4 + g*2 + b
    for (int i = tid; i < 1024; i += 512) {
        int g = i >> 9, rr = i & 511, kp = rr >> 1, b = rr & 1;
        hpb[g * 1024 + kp * 2 + b] =
            ((const ull*)hidden)[(size_t)(grp * 4 + g * 2 + b) * 256 + kp];
    }
    if (tid < 64) hub[tid] = hub_g[jjbase + tid];
    float zub = ztub[0], rub = rtub[0];
    if (tid == 0) {
#pragma unroll
        for (int m = 0; m < 32; m++) {
            asm volatile("mbarrier.init.shared.b64 [%0], %1;"
                         :: "r"(mbase + m * 8), "r"(1) : "memory");
        }
#pragma unroll
        for (int m = 0; m < 32; m++) {
            asm volatile("mbarrier.arrive.expect_tx.shared::cta.b64 _, [%0], %1;"
                         :: "r"(mbase + m * 8), "r"(512) : "memory");
        }
    }

    // remote targets (tids 0..7 -> peer ranks)
    unsigned dst_r = 0, mb_rb = 0;
    if (tid < 8) {
        unsigned rem;
        asm("mapa.shared::cluster.u32 %0, %1, %2;" : "=r"(rem) : "r"(hpb_a), "r"(tid));
        dst_r = rem + (unsigned)rank * 512u;    // our chunk slot (byte) within a buffer
        asm("mapa.shared::cluster.u32 %0, %1, %2;" : "=r"(mb_rb) : "r"(mbase), "r"(tid));
    }

    // step-0 input prefetch (both groups), phase4 threads only
    size_t ob[2] = {0, 0};
    float xnv[2] = {0.f, 0.f}, xzv[2] = {0.f, 0.f}, xrv[2] = {0.f, 0.f};
    int b2 = (tid >> 6) & 1;
    int jj4 = tid & 63;
    if (tid < 128) {
#pragma unroll
        for (int g = 0; g < 2; g++) {
            int row = grp * 4 + g * 2 + b2;
            ob[g] = (size_t)row * HH + jjbase + jj4;
            xnv[g] = out[ob[g]];
            xzv[g] = g_xz[row];
            xrv[g] = g_xr[row];
        }
    }

    __syncthreads();
    asm volatile("barrier.cluster.arrive.aligned;" ::: "memory");
    asm volatile("barrier.cluster.wait.aligned;" ::: "memory");

    unsigned pbits = 0;   // per-warp parity bits: bit (g*2+s)

#define SUBSTEP(G, BAR1, BARPD)                                               \
    do {                                                                      \
        int s = t & 1, sf = s ^ 1;                                            \
        if (t > 0) {                                                          \
            if (own) {                                                        \
                if (warp >= 4) bar_sync(BAR1, b1cnt);                         \
            } else {                                                          \
                unsigned mb = mbase + (((G) * 8 + chnk) * 2 + s) * 8u;        \
                if (lane == 0) {                                              \
                    int ph = (pbits >> ((G) * 2 + s)) & 1;                    \
                    unsigned done = 0;                                        \
                    while (!done) {                                           \
                        asm volatile(                                         \
                            "{\n\t.reg .pred p;\n\t"                          \
                            "mbarrier.try_wait.parity.acquire.cta.shared::cta.b64 p, [%1], %2, 0x989680;\n\t" \
                            "selp.b32 %0, 1, 0, p;\n\t}"                      \
                            : "=r"(done) : "r"(mb), "r"(ph) : "memory");      \
                    }                                                         \
                }                                                             \
                __syncwarp();                                                 \
                pbits ^= 1u << ((G) * 2 + s);                                 \
                if (gate == 0 && lane == 0) {                                 \
                    asm volatile("mbarrier.arrive.expect_tx.shared::cta.b64 _, [%0], %1;" \
                                 :: "r"(mb), "r"(512) : "memory");            \
                }                                                             \
            }                                                                 \
        }                                                                     \
        const ull* hg = hpb + (G) * 1024 + s * 512;                           \
        { /* gates */                                                         \
            int gkp = ks8 * 32 + lane;                                        \
            ull u = (gate ? rup : zup)[gkp];                                  \
            QU H; H.q = *(const uint4*)(hg + gkp * 2);                        \
            ull a0 = 0, a1 = 0;                                               \
            fma2(a0, H.u[0], u);                                              \
            fma2(a1, H.u[1], u);                                              \
            U64F2 c0, c1; c0.u = a0; c1.u = a1;                               \
            float s0 = c0.f.x + c0.f.y, s1 = c1.f.x + c1.f.y;                 \
            _Pragma("unroll")                                                 \
            for (int off = 16; off >= 1; off >>= 1) {                         \
                s0 += __shfl_xor_sync(0xffffffffu, s0, off);                  \
                s1 += __shfl_xor_sync(0xffffffffu, s1, off);                  \
            }                                                                 \
            if (lane == 0)                                                    \
                ((float2*)(zrpf + ((G) * 2 + s) * 32))[gate * 8 + ks8] =      \
                    make_float2(s0, s1);                                      \
        }                                                                     \
        { /* main dot */                                                      \
            const ull* hq = hg + ks * 32;                                     \
            ull a00 = 0, a01 = 0, a10 = 0, a11 = 0;                           \
            _Pragma("unroll")                                                 \
            for (int i = 0; i < 8; i++) {                                     \
                QU H; H.q = *(const uint4*)(hq + i * 2);                      \
                fma2(a00, wreg[2 * i],     H.u[0]);                           \
                fma2(a01, wreg[2 * i],     H.u[1]);                           \
                fma2(a10, wreg[2 * i + 1], H.u[0]);                           \
                fma2(a11, wreg[2 * i + 1], H.u[1]);                           \
            }                                                                 \
            _Pragma("unroll")                                                 \
            for (int i = 8; i < 16; i++) {                                    \
                QU Wq, H;                                                     \
                Wq.q = *(const uint4*)(wS + (ks * 8 + (i - 8)) * 64 + jjp * 2); \
                H.q  = *(const uint4*)(hq + i * 2);                           \
                fma2(a00, Wq.u[0], H.u[0]);                                   \
                fma2(a01, Wq.u[0], H.u[1]);                                   \
                fma2(a10, Wq.u[1], H.u[0]);                                   \
                fma2(a11, Wq.u[1], H.u[1]);                                   \
            }                                                                 \
            U64F2 u0, u1;                                                     \
            float2* pp = (float2*)(part + ((G) * 2 + s) * 2048);              \
            u0.u = a00; u1.u = a10;                                           \
            pp[ks * 64 + jjp]      = make_float2(u0.f.x + u0.f.y, u1.f.x + u1.f.y); \
            u0.u = a01; u1.u = a11;                                           \
            pp[ks * 64 + 32 + jjp] = make_float2(u0.f.x + u0.f.y, u1.f.x + u1.f.y); \
        }                                                                     \
        if (warp < 4) bar_sync((BARPD) + s, 512);                             \
        else          bar_arrive((BARPD) + s, 512);                           \
        if (tid < 128) { /* phase4: 64 jj x 2 b */                            \
            const float* ps = part + ((G) * 2 + s) * 2048;                    \
            float ssum = 0.f;                                                 \
            _Pragma("unroll")                                                 \
            for (int ki = 0; ki < 16; ki++) ssum += ps[ki * 128 + b2 * 64 + jj4]; \
            const float* zs = zrpf + ((G) * 2 + s) * 32;                      \
            float gz = 0.f, gr = 0.f;                                         \
            _Pragma("unroll")                                                 \
            for (int c = 0; c < 8; c++) {                                     \
                gz += zs[c * 2 + b2];                                         \
                gr += zs[(8 + c) * 2 + b2];                                   \
            }                                                                 \
            float zt = sigmoid_fast(xzv[G] + gz + zub);                       \
            float rt = sigmoid_fast(xrv[G] + gr + rub);                       \
            float nt = tanh_fast(fmaf(ssum + hub[jj4], rt, xnv[G]));          \
            U64F2 h2; h2.u = hg[((jjbase + jj4) >> 1) * 2 + b2];              \
            float hold = (jj4 & 1) ? h2.f.y : h2.f.x;                         \
            float hn = (1.f - zt) * nt + zt * hold;                           \
            out[ob[G]] = hn;                                                  \
            float hn1 = __shfl_down_sync(0xffffffffu, hn, 1);                 \
            if ((jj4 & 1) == 0)                                               \
                hpb[(G) * 1024 + sf * 512 + ((jjbase + jj4) >> 1) * 2 + b2] = \
                    pack2(hn, hn1);                                           \
            if (t < TT - 1) {                                                 \
                ob[G] += (size_t)BB * HH;                                     \
                xnv[G] = out[ob[G]];                                          \
                int row = (t + 1) * BB + grp * 4 + (G) * 2 + b2;              \
                xzv[G] = g_xz[row];                                           \
                xrv[G] = g_xr[row];                                           \
            } else if (tail >= BB * HH) {                                     \
                out[(size_t)TT * BB * HH +                                    \
                    (size_t)(grp * 4 + (G) * 2 + b2) * HH + jjbase + jj4] = hn; \
            }                                                                 \
        }                                                                     \
        if (t < TT - 1 && warp < 4) {                                         \
            bar_sync(BAR1, b1cnt);                                            \
            if (tid < 8 && tid != rank) {                                     \
                asm volatile("fence.proxy.async.shared::cta;" ::: "memory");  \
                unsigned boff = (unsigned)((G) * 8192 + sf * 4096);           \
                unsigned src = hpb_a + boff + (unsigned)rank * 512u;          \
                unsigned dst = dst_r + boff;                                  \
                unsigned mb  = mb_rb + (((G) * 8 + rank) * 2 + sf) * 8u;      \
                asm volatile(                                                 \
                    "cp.async.bulk.shared::cluster.shared::cta.mbarrier::complete_tx::bytes " \
                    "[%0], [%1], %2, [%3];"                                   \
                    :: "r"(dst), "r"(src), "r"(512u), "r"(mb) : "memory");    \
            }                                                                 \
        }                                                                     \
    } while (0)

    for (int t = 0; t < TT; t++) {
        SUBSTEP(0, 1, 8);
        SUBSTEP(1, 4, 10);
    }
#undef SUBSTEP

    // teardown: no CTA leaves while peers may still target its smem
    asm volatile("barrier.cluster.arrive.aligned;" ::: "memory");
    asm volatile("barrier.cluster.wait.aligned;" ::: "memory");
}

// ---------------- launch ----------------
extern "C" void kernel_launch(void* const* d_in, const int* in_sizes, int n_in,
                              void* d_out, int out_size) {
    const float* input  = (const float*)d_in[0];
    const float* hidden = (const float*)d_in[1];
    const float* zt_w_w = (const float*)d_in[2];
    const float* zt_w_b = (const float*)d_in[3];
    const float* zt_u_w = (const float*)d_in[4];
    const float* zt_u_b = (const float*)d_in[5];
    const float* rt_w_w = (const float*)d_in[6];
    const float* rt_w_b = (const float*)d_in[7];
    const float* rt_u_w = (const float*)d_in[8];
    const float* rt_u_b = (const float*)d_in[9];
    const float* h_w_w  = (const float*)d_in[10];
    const float* h_w_b  = (const float*)d_in[11];
    const float* h_u_w  = (const float*)d_in[12];
    const float* h_u_b  = (const float*)d_in[13];
    float* out = (float*)d_out;

    int tail = out_size - TT * BB * HH;

    gate_pre_kernel<<<TT * BB / 8, 256>>>(input, zt_w_w, zt_w_b, rt_w_w, rt_w_b);

    {
        dim3 grid(TT * BB / 128, HH / 64);
        xn_gemm_mma<<<grid, 256>>>(input, h_w_w, h_w_b, out);
    }

    static int smem_set = 0;
    if (!smem_set) {
        cudaFuncSetAttribute(scan_kernel, cudaFuncAttributeMaxDynamicSharedMemorySize, SC_SMEM);
        smem_set = 1;
    }
    scan_kernel<<<128, 512, SC_SMEM>>>(hidden, zt_u_w, zt_u_b, rt_u_w, rt_u_b,
                                       h_u_w, h_u_b, out, tail);
}

// round 17
// speedup vs baseline: 1.9914x; 1.9914x over previous
#include <cuda_runtime.h>
#include <cuda_bf16.h>
#include <math.h>

// Problem dims
#define TT 512
#define BB 64
#define II 512
#define HH 512

// ---------------- device scratch ----------------
__device__ float g_xz[TT * BB];   // [t][b] includes zt_w_b
__device__ float g_xr[TT * BB];   // [t][b] includes rt_w_b

// ---------------- helpers ----------------
typedef unsigned long long ull;
union U64F2 { ull u; float2 f; };
union QU    { uint4 q; ull u[2]; };

__device__ __forceinline__ void fma2(ull& d, ull a, ull b) {
    asm("fma.rn.f32x2 %0, %1, %2, %0;" : "+l"(d) : "l"(a), "l"(b));
}
__device__ __forceinline__ ull pack2(float lo, float hi) {
    ull r; asm("mov.b64 %0, {%1, %2};" : "=l"(r) : "f"(lo), "f"(hi)); return r;
}
__device__ __forceinline__ float sigmoid_fast(float x) {
    float e, r;
    asm("ex2.approx.f32 %0, %1;" : "=f"(e) : "f"(-1.4426950408889634f * x));
    asm("rcp.approx.f32 %0, %1;" : "=f"(r) : "f"(1.0f + e));
    return r;
}
__device__ __forceinline__ float tanh_fast(float x) {
    float e, r;
    asm("ex2.approx.f32 %0, %1;" : "=f"(e) : "f"(-2.8853900817779268f * x));
    asm("rcp.approx.f32 %0, %1;" : "=f"(r) : "f"(1.0f + e));
    return fmaf(2.0f, r, -1.0f);
}
__device__ __forceinline__ unsigned smem_u32(const void* p) {
    return (unsigned)__cvta_generic_to_shared(p);
}
__device__ __forceinline__ void bar_sync(int id, int cnt) {
    asm volatile("bar.sync %0, %1;" :: "r"(id), "r"(cnt) : "memory");
}
__device__ __forceinline__ void bar_arrive(int id, int cnt) {
    asm volatile("bar.arrive %0, %1;" :: "r"(id), "r"(cnt) : "memory");
}
__device__ __forceinline__ unsigned pack_bf16x2(float v_lo, float v_hi) {
    unsigned r;
    asm("cvt.rn.bf16x2.f32 %0, %1, %2;" : "=r"(r) : "f"(v_hi), "f"(v_lo));
    return r;
}

// ---------------- kernel 1: gate input projections xz, xr ----------------
__global__ void gate_pre_kernel(const float* __restrict__ in,
                                const float* __restrict__ zw, const float* __restrict__ zb,
                                const float* __restrict__ rw, const float* __restrict__ rb) {
    int row  = blockIdx.x * 8 + (threadIdx.x >> 5);
    int lane = threadIdx.x & 31;
    const float4* a4 = (const float4*)(in + (size_t)row * II);
    const float4* z4 = (const float4*)zw;
    const float4* r4 = (const float4*)rw;
    float az = 0.f, ar = 0.f;
#pragma unroll 4
    for (int i = lane; i < II / 4; i += 32) {
        float4 v = a4[i];
        float4 z = z4[i];
        float4 r = r4[i];
        az += v.x * z.x + v.y * z.y + v.z * z.z + v.w * z.w;
        ar += v.x * r.x + v.y * r.y + v.z * r.z + v.w * r.w;
    }
#pragma unroll
    for (int off = 16; off >= 1; off >>= 1) {
        az += __shfl_xor_sync(0xffffffffu, az, off);
        ar += __shfl_xor_sync(0xffffffffu, ar, off);
    }
    if (lane == 0) {
        g_xz[row] = az + zb[0];
        g_xr[row] = ar + rb[0];
    }
}

// ---------------- kernel 2: xn GEMM via mma.sync bf16, split-bf16 --------
// R15 GEMM + double-buffered global prefetch (registers) to hide LDG latency.
#define MMA_OP(c, a, b)                                                       \
    asm volatile("mma.sync.aligned.m16n8k16.row.col.f32.bf16.bf16.f32 "       \
                 "{%0,%1,%2,%3},{%4,%5,%6,%7},{%8,%9},{%0,%1,%2,%3};"         \
                 : "+f"(c[0]), "+f"(c[1]), "+f"(c[2]), "+f"(c[3])             \
                 : "r"(a[0]), "r"(a[1]), "r"(a[2]), "r"(a[3]),                \
                   "r"(b[0]), "r"(b[1]))

__global__ __launch_bounds__(256) void xn_gemm_mma(const float* __restrict__ A,
                                                   const float* __restrict__ W,
                                                   const float* __restrict__ bias,
                                                   float* __restrict__ C) {
    __shared__ __align__(16) unsigned short sAh[128 * 40];
    __shared__ __align__(16) unsigned short sAl[128 * 40];
    __shared__ __align__(16) unsigned short sWh[64 * 40];
    __shared__ __align__(16) unsigned short sWl[64 * 40];
    __shared__ __align__(16) float sBias[64];

    int tid  = threadIdx.x;
    int lane = tid & 31;
    int warp = tid >> 5;
    int wm   = warp >> 1;
    int wn   = warp & 1;
    int bm   = blockIdx.x * 128;
    int bn   = blockIdx.y * 64;

    if (tid < 64) sBias[tid] = bias[bn + tid];

    float acc[2][4][4];
#pragma unroll
    for (int i = 0; i < 2; i++)
#pragma unroll
        for (int j = 0; j < 4; j++)
#pragma unroll
            for (int q = 0; q < 4; q++) acc[i][j][q] = 0.f;

    int r  = lane >> 2;
    int g2 = (lane & 3) * 2;

    int rowA = tid >> 3, f4A = tid & 7;          // per-thread A slots (stride 32 rows)
    int rowW = tid >> 3, f4W = tid & 7;          // per-thread W slots (stride 32 rows)

    // preload chunk 0
    float4 pa[4], pw[2];
#pragma unroll
    for (int i = 0; i < 4; i++)
        pa[i] = *(const float4*)(A + (size_t)(bm + rowA + i * 32) * 512 + f4A * 4);
#pragma unroll
    for (int i = 0; i < 2; i++)
        pw[i] = *(const float4*)(W + (size_t)(bn + rowW + i * 32) * 512 + f4W * 4);

    for (int kc = 0; kc < 16; kc++) {
        // convert + store current chunk
#pragma unroll
        for (int i = 0; i < 4; i++) {
            int row = rowA + i * 32;
            float4 v = pa[i];
            float hx = __bfloat162float(__float2bfloat16(v.x));
            float hy = __bfloat162float(__float2bfloat16(v.y));
            float hz = __bfloat162float(__float2bfloat16(v.z));
            float hw = __bfloat162float(__float2bfloat16(v.w));
            *(unsigned*)(sAh + row * 40 + f4A * 4)     = pack_bf16x2(v.x, v.y);
            *(unsigned*)(sAh + row * 40 + f4A * 4 + 2) = pack_bf16x2(v.z, v.w);
            *(unsigned*)(sAl + row * 40 + f4A * 4)     = pack_bf16x2(v.x - hx, v.y - hy);
            *(unsigned*)(sAl + row * 40 + f4A * 4 + 2) = pack_bf16x2(v.z - hz, v.w - hw);
        }
#pragma unroll
        for (int i = 0; i < 2; i++) {
            int row = rowW + i * 32;
            float4 v = pw[i];
            float hx = __bfloat162float(__float2bfloat16(v.x));
            float hy = __bfloat162float(__float2bfloat16(v.y));
            float hz = __bfloat162float(__float2bfloat16(v.z));
            float hw = __bfloat162float(__float2bfloat16(v.w));
            *(unsigned*)(sWh + row * 40 + f4W * 4)     = pack_bf16x2(v.x, v.y);
            *(unsigned*)(sWh + row * 40 + f4W * 4 + 2) = pack_bf16x2(v.z, v.w);
            *(unsigned*)(sWl + row * 40 + f4W * 4)     = pack_bf16x2(v.x - hx, v.y - hy);
            *(unsigned*)(sWl + row * 40 + f4W * 4 + 2) = pack_bf16x2(v.z - hz, v.w - hw);
        }
        __syncthreads();

        // prefetch next chunk (overlaps with compute below)
        if (kc < 15) {
            int ko = (kc + 1) * 32;
#pragma unroll
            for (int i = 0; i < 4; i++)
                pa[i] = *(const float4*)(A + (size_t)(bm + rowA + i * 32) * 512 + ko + f4A * 4);
#pragma unroll
            for (int i = 0; i < 2; i++)
                pw[i] = *(const float4*)(W + (size_t)(bn + rowW + i * 32) * 512 + ko + f4W * 4);
        }

#pragma unroll
        for (int ks = 0; ks < 2; ks++) {
            int k0 = ks * 16;
            unsigned Ah[2][4], Al[2][4], Bh[4][2], Bl[4][2];
#pragma unroll
            for (int mi = 0; mi < 2; mi++) {
                int rb = wm * 32 + mi * 16;
                Ah[mi][0] = *(const unsigned*)(sAh + (rb + r) * 40 + k0 + g2);
                Ah[mi][1] = *(const unsigned*)(sAh + (rb + r + 8) * 40 + k0 + g2);
                Ah[mi][2] = *(const unsigned*)(sAh + (rb + r) * 40 + k0 + g2 + 8);
                Ah[mi][3] = *(const unsigned*)(sAh + (rb + r + 8) * 40 + k0 + g2 + 8);
                Al[mi][0] = *(const unsigned*)(sAl + (rb + r) * 40 + k0 + g2);
                Al[mi][1] = *(const unsigned*)(sAl + (rb + r + 8) * 40 + k0 + g2);
                Al[mi][2] = *(const unsigned*)(sAl + (rb + r) * 40 + k0 + g2 + 8);
                Al[mi][3] = *(const unsigned*)(sAl + (rb + r + 8) * 40 + k0 + g2 + 8);
            }
#pragma unroll
            for (int ni = 0; ni < 4; ni++) {
                int cb = wn * 32 + ni * 8 + r;
                Bh[ni][0] = *(const unsigned*)(sWh + cb * 40 + k0 + g2);
                Bh[ni][1] = *(const unsigned*)(sWh + cb * 40 + k0 + g2 + 8);
                Bl[ni][0] = *(const unsigned*)(sWl + cb * 40 + k0 + g2);
                Bl[ni][1] = *(const unsigned*)(sWl + cb * 40 + k0 + g2 + 8);
            }
#pragma unroll
            for (int mi = 0; mi < 2; mi++)
#pragma unroll
                for (int ni = 0; ni < 4; ni++) {
                    MMA_OP(acc[mi][ni], Ah[mi], Bh[ni]);
                    MMA_OP(acc[mi][ni], Ah[mi], Bl[ni]);
                    MMA_OP(acc[mi][ni], Al[mi], Bh[ni]);
                }
        }
        __syncthreads();
    }

#pragma unroll
    for (int mi = 0; mi < 2; mi++)
#pragma unroll
        for (int ni = 0; ni < 4; ni++) {
            int row = bm + wm * 32 + mi * 16 + r;
            int cl  = wn * 32 + ni * 8 + g2;
            int col = bn + cl;
            float2 o0, o1;
            o0.x = acc[mi][ni][0] + sBias[cl];
            o0.y = acc[mi][ni][1] + sBias[cl + 1];
            o1.x = acc[mi][ni][2] + sBias[cl];
            o1.y = acc[mi][ni][3] + sBias[cl + 1];
            *(float2*)(C + (size_t)row * 512 + col)       = o0;
            *(float2*)(C + (size_t)(row + 8) * 512 + col) = o1;
        }
}

// ---------------- kernel 3: recurrent scan (R15 proven, verbatim) --------
#define WS_OFF   0                        // float[128 kpc][128] = 64KB
#define HP_OFF   65536                    // ull[2][1024]  = 16KB
#define PART_OFF (HP_OFF + 16384)         // float[2][16][256] = 32KB
#define ZRP_OFF  (PART_OFF + 32768)       // float[2][64] = 512
#define ZUP_OFF  (ZRP_OFF + 512)          // ull[256]
#define RUP_OFF  (ZUP_OFF + 2048)         // ull[256]
#define HUB_OFF  (RUP_OFF + 2048)         // float[64]
#define MBAR_OFF (HUB_OFF + 256)          // 16 x b64 = [chunk c][buf s]
#define SC_SMEM  (MBAR_OFF + 128)

extern __shared__ char sc_smem[];

__global__ void __cluster_dims__(8, 1, 1) __launch_bounds__(512, 1)
scan_kernel(const float* __restrict__ hidden,
            const float* __restrict__ ztu_g, const float* __restrict__ ztub,
            const float* __restrict__ rtu_g, const float* __restrict__ rtub,
            const float* __restrict__ huw, const float* __restrict__ hub_g,
            float* __restrict__ out, int tail) {
    ull*   wS   = (ull*)(sc_smem + WS_OFF);
    ull*   hpb  = (ull*)(sc_smem + HP_OFF);
    float* part = (float*)(sc_smem + PART_OFF);   // [2][4096]
    float* zrpf = (float*)(sc_smem + ZRP_OFF);    // [2][64]
    ull*   zup  = (ull*)(sc_smem + ZUP_OFF);
    ull*   rup  = (ull*)(sc_smem + RUP_OFF);
    float* hub  = (float*)(sc_smem + HUB_OFF);

    int tid    = threadIdx.x;
    int rank   = blockIdx.x & 7;
    int grp    = blockIdx.x >> 3;
    int jjbase = rank * 64;
    unsigned mbase = smem_u32(sc_smem + MBAR_OFF);
    unsigned hpb_a = smem_u32(hpb);

    int lane = tid & 31;
    int warp = tid >> 5;
    int jjp  = lane;
    int ks   = warp;
    int gate = warp & 1;
    int ks8  = warp >> 1;
    int chnk = warp >> 1;
    int own  = (chnk == rank);
    int jj4  = tid & 63;
    int b4   = (tid >> 6) & 3;
    int b1cnt = (rank >= 4) ? 320 : 256;

    // -------- prologue --------
    for (int i = tid; i < 64 * 512; i += 512) {
        int jj = i >> 9, k = i & 511;
        int kp = k >> 1, kpl = kp & 15;
        if (kpl >= 8) {
            int kpc = (kp >> 4) * 8 + (kpl - 8);
            ((float*)wS)[kpc * 128 + jj * 2 + (k & 1)] = huw[(size_t)(jjbase + jj) * HH + k];
        }
    }
    ull wreg[16];
    {
        const float* wr0 = huw + (size_t)(jjbase + 2 * jjp) * HH + ks * 32;
        const float* wr1 = wr0 + HH;
#pragma unroll
        for (int i = 0; i < 8; i++) {
            wreg[2 * i]     = *(const ull*)(wr0 + 2 * i);
            wreg[2 * i + 1] = *(const ull*)(wr1 + 2 * i);
        }
    }
    if (tid < 256) zup[tid] = ((const ull*)ztu_g)[tid];
    else           rup[tid - 256] = ((const ull*)rtu_g)[tid - 256];
    for (int i = tid; i < 1024; i += 512) {
        hpb[i] = ((const ull*)hidden)[(size_t)(grp * 4 + (i & 3)) * 256 + (i >> 2)];
    }
    if (tid < 64) hub[tid] = hub_g[jjbase + tid];
    float zub = ztub[0], rub = rtub[0];
    if (tid == 0) {
#pragma unroll
        for (int m = 0; m < 16; m++) {
            asm volatile("mbarrier.init.shared.b64 [%0], %1;"
                         :: "r"(mbase + m * 8), "r"(1) : "memory");
        }
#pragma unroll
        for (int m = 0; m < 16; m++) {
            asm volatile("mbarrier.arrive.expect_tx.shared::cta.b64 _, [%0], %1;"
                         :: "r"(mbase + m * 8), "r"(1024) : "memory");
        }
    }

    unsigned dst_r = 0, mb_r = 0;
    if (tid < 8) {
        unsigned rem;
        asm("mapa.shared::cluster.u32 %0, %1, %2;" : "=r"(rem) : "r"(hpb_a), "r"(tid));
        dst_r = rem + (unsigned)rank * 1024u;
        asm("mapa.shared::cluster.u32 %0, %1, %2;" : "=r"(rem) : "r"(mbase), "r"(tid));
        mb_r = rem + (unsigned)rank * 16u;
    }

    size_t obase = 0;
    float xnv = 0.f, xzv = 0.f, xrv = 0.f;
    if (tid < 256) {
        obase = (size_t)(grp * 4 + b4) * HH + jjbase + jj4;
        xnv = out[obase];
        xzv = g_xz[grp * 4 + b4];
        xrv = g_xr[grp * 4 + b4];
    }

    __syncthreads();
    asm volatile("barrier.cluster.arrive.aligned;" ::: "memory");
    asm volatile("barrier.cluster.wait.aligned;" ::: "memory");

    int p0 = 0, p1 = 0;
    unsigned mb_c = mbase + (unsigned)chnk * 16u;

    for (int t = 0; t < TT; t++) {
        int s = t & 1, sf = s ^ 1;

        if (t > 0) {
            if (own) {
                if (warp >= 8) bar_sync(1, b1cnt);
            } else {
                if (lane == 0) {
                    int ph = s ? p1 : p0;
                    unsigned done = 0;
                    while (!done) {
                        asm volatile(
                            "{\n\t.reg .pred p;\n\t"
                            "mbarrier.try_wait.parity.acquire.cta.shared::cta.b64 p, [%1], %2, 0x989680;\n\t"
                            "selp.b32 %0, 1, 0, p;\n\t}"
                            : "=r"(done) : "r"(mb_c + (unsigned)s * 8u), "r"(ph) : "memory");
                    }
                }
                __syncwarp();
                if (s) p1 ^= 1; else p0 ^= 1;
                if (gate == 0 && lane == 0) {
                    asm volatile("mbarrier.arrive.expect_tx.shared::cta.b64 _, [%0], %1;"
                                 :: "r"(mb_c + (unsigned)s * 8u), "r"(1024) : "memory");
                }
            }
        }

        const ull* hp = hpb + s * 1024;

        {
            int gkp = ks8 * 32 + lane;
            ull u = (gate ? rup : zup)[gkp];
            QU A, B;
            A.q = *(const uint4*)(hp + gkp * 4);
            B.q = *(const uint4*)(hp + gkp * 4 + 2);
            ull a0 = 0, a1 = 0, a2 = 0, a3 = 0;
            fma2(a0, A.u[0], u);
            fma2(a1, A.u[1], u);
            fma2(a2, B.u[0], u);
            fma2(a3, B.u[1], u);
            U64F2 c0, c1, c2, c3;
            c0.u = a0; c1.u = a1; c2.u = a2; c3.u = a3;
            float s0 = c0.f.x + c0.f.y, s1 = c1.f.x + c1.f.y;
            float s2 = c2.f.x + c2.f.y, s3 = c3.f.x + c3.f.y;
#pragma unroll
            for (int off = 16; off >= 1; off >>= 1) {
                s0 += __shfl_xor_sync(0xffffffffu, s0, off);
                s1 += __shfl_xor_sync(0xffffffffu, s1, off);
                s2 += __shfl_xor_sync(0xffffffffu, s2, off);
                s3 += __shfl_xor_sync(0xffffffffu, s3, off);
            }
            if (lane == 0)
                ((float4*)(zrpf + s * 64))[gate * 8 + ks8] = make_float4(s0, s1, s2, s3);
        }

        {
            const ull* hq = hp + ks * 64;
            ull a00 = 0, a01v = 0, a02 = 0, a03 = 0;
            ull a10 = 0, a11v = 0, a12 = 0, a13 = 0;
#pragma unroll
            for (int i = 0; i < 8; i++) {
                QU Ha, Hb;
                Ha.q = *(const uint4*)(hq + i * 4);
                Hb.q = *(const uint4*)(hq + i * 4 + 2);
                fma2(a00,  wreg[2 * i],     Ha.u[0]);
                fma2(a01v, wreg[2 * i],     Ha.u[1]);
                fma2(a02,  wreg[2 * i],     Hb.u[0]);
                fma2(a03,  wreg[2 * i],     Hb.u[1]);
                fma2(a10,  wreg[2 * i + 1], Ha.u[0]);
                fma2(a11v, wreg[2 * i + 1], Ha.u[1]);
                fma2(a12,  wreg[2 * i + 1], Hb.u[0]);
                fma2(a13,  wreg[2 * i + 1], Hb.u[1]);
            }
#pragma unroll
            for (int i = 8; i < 16; i++) {
                QU Wq, Ha, Hb;
                Wq.q = *(const uint4*)(wS + (ks * 8 + (i - 8)) * 64 + jjp * 2);
                Ha.q = *(const uint4*)(hq + i * 4);
                Hb.q = *(const uint4*)(hq + i * 4 + 2);
                fma2(a00,  Wq.u[0], Ha.u[0]);
                fma2(a01v, Wq.u[0], Ha.u[1]);
                fma2(a02,  Wq.u[0], Hb.u[0]);
                fma2(a03,  Wq.u[0], Hb.u[1]);
                fma2(a10,  Wq.u[1], Ha.u[0]);
                fma2(a11v, Wq.u[1], Ha.u[1]);
                fma2(a12,  Wq.u[1], Hb.u[0]);
                fma2(a13,  Wq.u[1], Hb.u[1]);
            }
            U64F2 u0, u1;
            float2* pp = (float2*)(part + s * 4096);
            u0.u = a00;  u1.u = a10;
            pp[ks * 128 + 0 * 32 + jjp] = make_float2(u0.f.x + u0.f.y, u1.f.x + u1.f.y);
            u0.u = a01v; u1.u = a11v;
            pp[ks * 128 + 1 * 32 + jjp] = make_float2(u0.f.x + u0.f.y, u1.f.x + u1.f.y);
            u0.u = a02;  u1.u = a12;
            pp[ks * 128 + 2 * 32 + jjp] = make_float2(u0.f.x + u0.f.y, u1.f.x + u1.f.y);
            u0.u = a03;  u1.u = a13;
            pp[ks * 128 + 3 * 32 + jjp] = make_float2(u0.f.x + u0.f.y, u1.f.x + u1.f.y);
        }

        if (warp < 8) bar_sync(2 + s, 512);
        else          bar_arrive(2 + s, 512);

        if (tid < 256) {
            const float* ps = part + s * 4096;
            float ssum = 0.f;
#pragma unroll
            for (int ki = 0; ki < 16; ki++) ssum += ps[ki * 256 + b4 * 64 + jj4];
            const float* zs = zrpf + s * 64;
            float gz = 0.f, gr = 0.f;
#pragma unroll
            for (int k8 = 0; k8 < 8; k8++) {
                gz += zs[k8 * 4 + b4];
                gr += zs[32 + k8 * 4 + b4];
            }
            float zt = sigmoid_fast(xzv + gz + zub);
            float rt = sigmoid_fast(xrv + gr + rub);
            float nt = tanh_fast(fmaf(ssum + hub[jj4], rt, xnv));
            U64F2 hold2; hold2.u = hp[((jjbase + jj4) >> 1) * 4 + b4];
            float hold = (jj4 & 1) ? hold2.f.y : hold2.f.x;
            float hn = (1.f - zt) * nt + zt * hold;

            out[obase] = hn;
            float hn1 = __shfl_down_sync(0xffffffffu, hn, 1);
            if ((jj4 & 1) == 0)
                hpb[sf * 1024 + ((jjbase + jj4) >> 1) * 4 + b4] = pack2(hn, hn1);

            if (t < TT - 1) {
                obase += (size_t)BB * HH;
                xnv = out[obase];
                xzv = g_xz[(t + 1) * BB + grp * 4 + b4];
                xrv = g_xr[(t + 1) * BB + grp * 4 + b4];
            } else if (tail >= BB * HH) {
                out[(size_t)TT * BB * HH + (size_t)(grp * 4 + b4) * HH + jjbase + jj4] = hn;
            }
        }

        if (t < TT - 1 && warp < 8) {
            bar_sync(1, b1cnt);
            if (tid < 8 && tid != rank) {
                asm volatile("fence.proxy.async.shared::cta;" ::: "memory");
                unsigned src = hpb_a + (unsigned)sf * 8192u + (unsigned)rank * 1024u;
                unsigned dst = dst_r + (unsigned)sf * 8192u;
                unsigned mb  = mb_r + (unsigned)sf * 8u;
                asm volatile(
                    "cp.async.bulk.shared::cluster.shared::cta.mbarrier::complete_tx::bytes "
                    "[%0], [%1], %2, [%3];"
                    :: "r"(dst), "r"(src), "r"(1024u), "r"(mb) : "memory");
            }
        }
    }

    asm volatile("barrier.cluster.arrive.aligned;" ::: "memory");
    asm volatile("barrier.cluster.wait.aligned;" ::: "memory");
}

// ---------------- launch ----------------
extern "C" void kernel_launch(void* const* d_in, const int* in_sizes, int n_in,
                              void* d_out, int out_size) {
    const float* input  = (const float*)d_in[0];
    const float* hidden = (const float*)d_in[1];
    const float* zt_w_w = (const float*)d_in[2];
    const float* zt_w_b = (const float*)d_in[3];
    const float* zt_u_w = (const float*)d_in[4];
    const float* zt_u_b = (const float*)d_in[5];
    const float* rt_w_w = (const float*)d_in[6];
    const float* rt_w_b = (const float*)d_in[7];
    const float* rt_u_w = (const float*)d_in[8];
    const float* rt_u_b = (const float*)d_in[9];
    const float* h_w_w  = (const float*)d_in[10];
    const float* h_w_b  = (const float*)d_in[11];
    const float* h_u_w  = (const float*)d_in[12];
    const float* h_u_b  = (const float*)d_in[13];
    float* out = (float*)d_out;

    int tail = out_size - TT * BB * HH;

    gate_pre_kernel<<<TT * BB / 8, 256>>>(input, zt_w_w, zt_w_b, rt_w_w, rt_w_b);

    {
        dim3 grid(TT * BB / 128, HH / 64);
        xn_gemm_mma<<<grid, 256>>>(input, h_w_w, h_w_b, out);
    }

    static int smem_set = 0;
    if (!smem_set) {
        cudaFuncSetAttribute(scan_kernel, cudaFuncAttributeMaxDynamicSharedMemorySize, SC_SMEM);
        smem_set = 1;
    }
    scan_kernel<<<128, 512, SC_SMEM>>>(hidden, zt_u_w, zt_u_b, rt_u_w, rt_u_b,
                                       h_u_w, h_u_b, out, tail);
}